// round 15
// baseline (speedup 1.0000x reference)
#include <cuda_runtime.h>
#include <cuda_fp16.h>
#include <cstdint>

#define B_ 2
#define N_ 65536
#define C_ 256
#define TS 32            // tokens per chunk
#define PC 37            // CTAs per (b,h) pair -> 592 CTAs
#define NCHUNK (N_/TS)   // 2048

// ---- scratch ----
__device__ float g_T[2*8*64*64];
__device__ float g_norm[2*8*64];
__device__ float g_We[8*256*64];       // W_x(head) @ W_slice folded (fp32)
__device__ float g_be[8*64];

__global__ void prep_kernel(const float* __restrict__ W_x, const float* __restrict__ b_x,
                            const float* __restrict__ W_slice, const float* __restrict__ b_slice) {
    int idx = blockIdx.x * blockDim.x + threadIdx.x;
    if (idx < 2*8*64*64) g_T[idx] = 0.f;
    if (idx < 2*8*64)    g_norm[idx] = 0.f;
    if (idx < 8*256*64) {
        int s = idx & 63, c = (idx >> 6) & 255, h = idx >> 14;
        float acc = 0.f;
        #pragma unroll
        for (int d = 0; d < 64; d++)
            acc += W_x[c*512 + h*64 + d] * W_slice[d*64 + s];
        g_We[idx] = acc;
    }
    if (idx < 8*64) {
        int s = idx & 63, h = idx >> 6;
        float acc = b_slice[s];
        #pragma unroll
        for (int d = 0; d < 64; d++)
            acc += b_x[h*64 + d] * W_slice[d*64 + s];
        g_be[idx] = acc;
    }
}

__device__ __forceinline__ void mma_f16(float* c, const uint32_t* a, const uint32_t* b) {
    asm volatile("mma.sync.aligned.m16n8k16.row.col.f32.f16.f16.f32 "
                 "{%0,%1,%2,%3},{%4,%5,%6,%7},{%8,%9},{%0,%1,%2,%3};"
                 : "+f"(c[0]), "+f"(c[1]), "+f"(c[2]), "+f"(c[3])
                 : "r"(a[0]), "r"(a[1]), "r"(a[2]), "r"(a[3]), "r"(b[0]), "r"(b[1]));
}
__device__ __forceinline__ void ldsm4(uint32_t* r, uint32_t addr) {
    asm volatile("ldmatrix.sync.aligned.m8n8.x4.shared.b16 {%0,%1,%2,%3}, [%4];"
        : "=r"(r[0]), "=r"(r[1]), "=r"(r[2]), "=r"(r[3]) : "r"(addr));
}
__device__ __forceinline__ uint32_t h2u(__half2 h) { return *(uint32_t*)&h; }
__device__ __forceinline__ uint32_t smem_u32(const void* p) {
    uint32_t a;
    asm("{ .reg .u64 t; cvta.to.shared.u64 t, %1; cvt.u32.u64 %0, t; }" : "=r"(a) : "l"(p));
    return a;
}

// SMEM layout (32-bit words):
//  sWe2  [64 n][132 kp] half2   @ 0       (8448)
//  sWfx2 [64 n][132 kp] half2   @ 8448    (8448)
//  sX2   [32 tok][132 kp] half2 @ 16896   (4224)
//  sFx   [32 t][68 d] fp32      @ 21120   (2176)
//  sWs   [32 t][68 s] fp32      @ 23296   (2176)  logits -> softmax weights in place
//  sBe   [64] @ 25472
//  sBfx  [64] @ 25536
#define OW_WE   0
#define OW_WFX  8448
#define OW_X    16896
#define OW_FX   21120
#define OW_WS   23296
#define OW_BE   25472
#define OW_BFX  25536
#define SMEM_WORDS 25600   // 102400 bytes -> 2 CTAs/SM

extern __shared__ float sm[];

__global__ void __launch_bounds__(256, 2)
fused_kernel(const float* __restrict__ x, const float* __restrict__ W_fx,
             const float* __restrict__ b_fx, const float* __restrict__ temperature) {
    uint32_t* sWe2  = (uint32_t*)sm + OW_WE;
    uint32_t* sWfx2 = (uint32_t*)sm + OW_WFX;
    uint32_t* sX2   = (uint32_t*)sm + OW_X;
    float*    sFx   = sm + OW_FX;
    float*    sWs   = sm + OW_WS;
    float*    sBe   = sm + OW_BE;
    float*    sBfx  = sm + OW_BFX;

    const int tid  = threadIdx.x;
    const int pair = blockIdx.x / PC;      // b*8 + h
    const int cidx = blockIdx.x % PC;
    const int b = pair >> 3, h = pair & 7;

    // stage weights n-major as half2 along k: W2[n][kp] = (w[2kp][n], w[2kp+1][n])
    for (int g = tid; g < 8192; g += 256) {
        int n = g & 63, kp = g >> 6;
        sWe2[n*132 + kp] = h2u(__floats2half2_rn(g_We[h*16384 + (2*kp)*64 + n],
                                                 g_We[h*16384 + (2*kp+1)*64 + n]));
        sWfx2[n*132 + kp] = h2u(__floats2half2_rn(W_fx[(2*kp)*512 + h*64 + n],
                                                  W_fx[(2*kp+1)*512 + h*64 + n]));
    }
    // zero phase-4 buffers so the first fused iteration adds zeros
    for (int g = tid; g < 4352; g += 256) sm[OW_FX + g] = 0.f;
    if (tid < 64) {
        sBe[tid]  = g_be[h*64 + tid];
        sBfx[tid] = b_fx[h*64 + tid];
    }
    float tmp = temperature[h];
    tmp = fminf(fmaxf(tmp, 0.5f), 5.0f);
    const float invT = 1.0f / tmp;

    const int warp = tid >> 5, lane = tid & 31;
    const int lg4 = lane >> 2, lm4 = lane & 3;

    const int mat = warp >> 2;             // 0: logits(We), 1: fx(Wfx)
    const int n0  = (warp & 3) * 16;

    // phase-4 (FFMA) thread mapping: 16 s-rows x 1 d-col per thread
    const int dcol  = tid & 63;
    const int sbase = (tid >> 6) << 4;     // 0,16,32,48

    // phase-2 ldmatrix per-lane addresses (bytes, shared space)
    const uint32_t sb = smem_u32(sm);
    const int Lm  = lane & 15;
    const int hiK = lane >> 4;
    const uint32_t aA = sb + (uint32_t)(OW_X + Lm*132 + hiK*4) * 4u;
    const uint32_t aB = sb + (uint32_t)((mat ? OW_WFX : OW_WE) + (n0 + Lm)*132 + hiK*4) * 4u;

    float accT[16];
    #pragma unroll
    for (int i = 0; i < 16; i++) accT[i] = 0.f;
    float accN = 0.f;

    const float* xbase = x + (size_t)b * N_ * C_;

    // ---- prologue: stage first x tile ----
    {
        const float* xp = xbase + (size_t)cidx * TS * C_;
        for (int g = tid; g < 2048; g += 256) {
            float4 v = ((const float4*)xp)[g];
            int row = g >> 6, kp0 = (g & 63) << 1;
            uint2 u;
            u.x = h2u(__floats2half2_rn(v.x, v.y));
            u.y = h2u(__floats2half2_rn(v.z, v.w));
            *(uint2*)&sX2[row*132 + kp0] = u;
        }
    }
    __syncthreads();

    for (int chunk = cidx; chunk < NCHUNK; chunk += PC) {
        // ---- fused: phase-2 MMA (chunk) + phase-4 FFMA (prev chunk) ----
        float c2[2][2][4];
        #pragma unroll
        for (int m = 0; m < 2; m++)
            #pragma unroll
            for (int n = 0; n < 2; n++)
                #pragma unroll
                for (int j = 0; j < 4; j++) c2[m][n][j] = 0.f;

        #pragma unroll
        for (int ks = 0; ks < 16; ks++) {
            uint32_t A0[4], A1[4], Bv[4];
            ldsm4(A0, aA + ks*32u);
            ldsm4(A1, aA + ks*32u + 16u*132u*4u);
            ldsm4(Bv, aB + ks*32u);
            uint32_t b0[2] = { Bv[0], Bv[2] };
            uint32_t b1[2] = { Bv[1], Bv[3] };
            mma_f16(c2[0][0], A0, b0);
            mma_f16(c2[0][1], A0, b1);
            mma_f16(c2[1][0], A1, b0);
            mma_f16(c2[1][1], A1, b1);
            // phase-4 of previous chunk: 2 tokens per k-step (fills tensor shadow)
            #pragma unroll
            for (int tt = 0; tt < 2; tt++) {
                int t = 2*ks + tt;
                float fv = sFx[t*68 + dcol];
                const float4* wr = (const float4*)&sWs[t*68 + sbase];
                float4 w0 = wr[0], w1 = wr[1], w2 = wr[2], w3 = wr[3];
                accT[0]  += w0.x*fv; accT[1]  += w0.y*fv; accT[2]  += w0.z*fv; accT[3]  += w0.w*fv;
                accT[4]  += w1.x*fv; accT[5]  += w1.y*fv; accT[6]  += w1.z*fv; accT[7]  += w1.w*fv;
                accT[8]  += w2.x*fv; accT[9]  += w2.y*fv; accT[10] += w2.z*fv; accT[11] += w2.w*fv;
                accT[12] += w3.x*fv; accT[13] += w3.y*fv; accT[14] += w3.z*fv; accT[15] += w3.w*fv;
            }
            if (tid < 64)
                accN += sWs[(2*ks)*68 + tid] + sWs[(2*ks+1)*68 + tid];
        }
        __syncthreads();   // MMA reads of sX2 + FFMA reads of sWs/sFx complete

        // ---- epilogue: logits -> sWs (raw fp32); fx -> sFx (fp32, bias added) ----
        #pragma unroll
        for (int m = 0; m < 2; m++) {
            #pragma unroll
            for (int nt = 0; nt < 2; nt++) {
                int r = m*16 + lg4;
                int cc = n0 + nt*8 + (lm4 << 1);
                if (mat == 0) {
                    *(float2*)&sWs[r*68 + cc]     = make_float2(c2[m][nt][0], c2[m][nt][1]);
                    *(float2*)&sWs[(r+8)*68 + cc] = make_float2(c2[m][nt][2], c2[m][nt][3]);
                } else {
                    float2 bv = *(float2*)&sBfx[cc];
                    *(float2*)&sFx[r*68 + cc] =
                        make_float2(c2[m][nt][0] + bv.x, c2[m][nt][1] + bv.y);
                    *(float2*)&sFx[(r+8)*68 + cc] =
                        make_float2(c2[m][nt][2] + bv.x, c2[m][nt][3] + bv.y);
                }
            }
        }

        // ---- stage next x tile ----
        int nchunk = chunk + PC;
        if (nchunk < NCHUNK) {
            const float* xp = xbase + (size_t)nchunk * TS * C_;
            for (int g = tid; g < 2048; g += 256) {
                float4 v = ((const float4*)xp)[g];
                int row = g >> 6, kp0 = (g & 63) << 1;
                uint2 u;
                u.x = h2u(__floats2half2_rn(v.x, v.y));
                u.y = h2u(__floats2half2_rn(v.z, v.w));
                *(uint2*)&sX2[row*132 + kp0] = u;
            }
        }
        __syncthreads();   // logits visible for softmax

        // ---- phase 3: softmax over 64 slices, in place in sWs ----
        {
            float2 be = *(float2*)&sBe[lane << 1];
            #pragma unroll
            for (int i = 0; i < 4; i++) {
                int t = warp*4 + i;
                float2 lg = *(float2*)&sWs[t*68 + (lane << 1)];
                float l0 = (lg.x + be.x) * invT;
                float l1 = (lg.y + be.y) * invT;
                float m = fmaxf(l0, l1);
                #pragma unroll
                for (int off = 16; off; off >>= 1)
                    m = fmaxf(m, __shfl_xor_sync(0xffffffffu, m, off));
                float e0 = __expf(l0 - m), e1 = __expf(l1 - m);
                float ss = e0 + e1;
                #pragma unroll
                for (int off = 16; off; off >>= 1)
                    ss += __shfl_xor_sync(0xffffffffu, ss, off);
                float inv = __frcp_rn(ss);
                *(float2*)&sWs[t*68 + (lane << 1)] = make_float2(e0*inv, e1*inv);
            }
        }
        __syncthreads();   // weights + fx + next x visible for next fused loop
    }

    // ---- tail: phase-4 FFMA for the final chunk ----
    #pragma unroll 4
    for (int t = 0; t < 32; t++) {
        float fv = sFx[t*68 + dcol];
        const float4* wr = (const float4*)&sWs[t*68 + sbase];
        float4 w0 = wr[0], w1 = wr[1], w2 = wr[2], w3 = wr[3];
        accT[0]  += w0.x*fv; accT[1]  += w0.y*fv; accT[2]  += w0.z*fv; accT[3]  += w0.w*fv;
        accT[4]  += w1.x*fv; accT[5]  += w1.y*fv; accT[6]  += w1.z*fv; accT[7]  += w1.w*fv;
        accT[8]  += w2.x*fv; accT[9]  += w2.y*fv; accT[10] += w2.z*fv; accT[11] += w2.w*fv;
        accT[12] += w3.x*fv; accT[13] += w3.y*fv; accT[14] += w3.z*fv; accT[15] += w3.w*fv;
    }
    if (tid < 64) {
        #pragma unroll 8
        for (int t = 0; t < 32; t++) accN += sWs[t*68 + tid];
    }

    // ---- flush partials ----
    float* dst = g_T + pair * 4096;
    #pragma unroll
    for (int i = 0; i < 16; i++)
        atomicAdd(&dst[(sbase + i)*64 + dcol], accT[i]);
    if (tid < 64) atomicAdd(&g_norm[pair*64 + tid], accN);
}

// K2: final normalization
__global__ void norm_kernel(float* __restrict__ out) {
    int idx = blockIdx.x * blockDim.x + threadIdx.x;
    int ps = idx >> 6;
    out[idx] = g_T[idx] / (g_norm[ps] + 0.01f);
}

extern "C" void kernel_launch(void* const* d_in, const int* in_sizes, int n_in,
                              void* d_out, int out_size) {
    const float* x    = (const float*)d_in[0];
    const float* W_x  = (const float*)d_in[1];
    const float* b_x  = (const float*)d_in[2];
    const float* W_fx = (const float*)d_in[3];
    const float* b_fx = (const float*)d_in[4];
    const float* W_s  = (const float*)d_in[5];
    const float* b_s  = (const float*)d_in[6];
    const float* temp = (const float*)d_in[7];
    float* out = (float*)d_out;

    cudaFuncSetAttribute(fused_kernel, cudaFuncAttributeMaxDynamicSharedMemorySize,
                         SMEM_WORDS * (int)sizeof(float));

    prep_kernel<<<512, 256>>>(W_x, b_x, W_s, b_s);
    fused_kernel<<<16 * PC, 256, SMEM_WORDS * sizeof(float)>>>(x, W_fx, b_fx, temp);
    norm_kernel<<<256, 256>>>(out);
}

// round 16
// speedup vs baseline: 1.5093x; 1.5093x over previous
#include <cuda_runtime.h>
#include <cuda_fp16.h>
#include <cstdint>

#define B_ 2
#define N_ 65536
#define C_ 256
#define TS 32            // tokens per chunk
#define PC 37            // CTAs per (b,h) pair -> 592 CTAs = 4 waves
#define NCHUNK (N_/TS)   // 2048

// ---- scratch ----
__device__ float g_T[2*8*64*64];
__device__ float g_norm[2*8*64];
__device__ float g_We[8*256*64];       // W_x(head) @ W_slice folded (fp32)
__device__ float g_be[8*64];

__global__ void prep_kernel(const float* __restrict__ W_x, const float* __restrict__ b_x,
                            const float* __restrict__ W_slice, const float* __restrict__ b_slice) {
    int idx = blockIdx.x * blockDim.x + threadIdx.x;
    if (idx < 2*8*64*64) g_T[idx] = 0.f;
    if (idx < 2*8*64)    g_norm[idx] = 0.f;
    if (idx < 8*256*64) {
        int s = idx & 63, c = (idx >> 6) & 255, h = idx >> 14;
        float acc = 0.f;
        #pragma unroll
        for (int d = 0; d < 64; d++)
            acc += W_x[c*512 + h*64 + d] * W_slice[d*64 + s];
        g_We[idx] = acc;
    }
    if (idx < 8*64) {
        int s = idx & 63, h = idx >> 6;
        float acc = b_slice[s];
        #pragma unroll
        for (int d = 0; d < 64; d++)
            acc += b_x[h*64 + d] * W_slice[d*64 + s];
        g_be[idx] = acc;
    }
}

__device__ __forceinline__ void mma_f16(float* c, const uint32_t* a, const uint32_t* b) {
    asm volatile("mma.sync.aligned.m16n8k16.row.col.f32.f16.f16.f32 "
                 "{%0,%1,%2,%3},{%4,%5,%6,%7},{%8,%9},{%0,%1,%2,%3};"
                 : "+f"(c[0]), "+f"(c[1]), "+f"(c[2]), "+f"(c[3])
                 : "r"(a[0]), "r"(a[1]), "r"(a[2]), "r"(a[3]), "r"(b[0]), "r"(b[1]));
}
__device__ __forceinline__ void ldsm4(uint32_t* r, uint32_t addr) {
    asm volatile("ldmatrix.sync.aligned.m8n8.x4.shared.b16 {%0,%1,%2,%3}, [%4];"
        : "=r"(r[0]), "=r"(r[1]), "=r"(r[2]), "=r"(r[3]) : "r"(addr));
}
__device__ __forceinline__ void ldsm4t(uint32_t* r, uint32_t addr) {
    asm volatile("ldmatrix.sync.aligned.m8n8.x4.trans.shared.b16 {%0,%1,%2,%3}, [%4];"
        : "=r"(r[0]), "=r"(r[1]), "=r"(r[2]), "=r"(r[3]) : "r"(addr));
}
__device__ __forceinline__ uint32_t h2u(__half2 h) { return *(uint32_t*)&h; }
__device__ __forceinline__ uint32_t smem_u32(const void* p) {
    uint32_t a;
    asm("{ .reg .u64 t; cvta.to.shared.u64 t, %1; cvt.u32.u64 %0, t; }" : "=r"(a) : "l"(p));
    return a;
}

// SMEM layout (32-bit words):
//  sWe2  [64 n][132 kp] half2  @ 0       (8448)
//  sWfx2 [64 n][132 kp] half2  @ 8448    (8448)
//  sX2   [32 tok][132 kp] half2 @ 16896  (4224)
//  sWh   [32 t][72 s] half     @ 21120   (1152)
//  sFh   [32 t][72 d] half     @ 22272   (1152)
//  sLG   [32 t][72 s] fp32     @ 23424   (2304)
//  sBe   [64] @ 25728
//  sBfx  [64] @ 25792
#define OW_WE   0
#define OW_WFX  8448
#define OW_X    16896
#define OW_WH   21120
#define OW_FH   22272
#define OW_LG   23424
#define OW_BE   25728
#define OW_BFX  25792
#define SMEM_WORDS 25856   // 103424 bytes -> 2 CTAs/SM

extern __shared__ float sm[];

__global__ void __launch_bounds__(256, 2)
fused_kernel(const float* __restrict__ x, const float* __restrict__ W_fx,
             const float* __restrict__ b_fx, const float* __restrict__ temperature) {
    uint32_t* sWe2  = (uint32_t*)sm + OW_WE;
    uint32_t* sWfx2 = (uint32_t*)sm + OW_WFX;
    uint32_t* sX2   = (uint32_t*)sm + OW_X;
    __half*   sWh   = (__half*)(sm + OW_WH);
    __half*   sFh   = (__half*)(sm + OW_FH);
    float*    sLG   = sm + OW_LG;
    float*    sBe   = sm + OW_BE;
    float*    sBfx  = sm + OW_BFX;

    const int tid  = threadIdx.x;
    const int pair = blockIdx.x / PC;      // b*8 + h
    const int cidx = blockIdx.x % PC;
    const int b = pair >> 3, h = pair & 7;

    // stage weights n-major as half2 along k: W2[n][kp] = (w[2kp][n], w[2kp+1][n])
    for (int g = tid; g < 8192; g += 256) {
        int n = g & 63, kp = g >> 6;
        sWe2[n*132 + kp] = h2u(__floats2half2_rn(g_We[h*16384 + (2*kp)*64 + n],
                                                 g_We[h*16384 + (2*kp+1)*64 + n]));
        sWfx2[n*132 + kp] = h2u(__floats2half2_rn(W_fx[(2*kp)*512 + h*64 + n],
                                                  W_fx[(2*kp+1)*512 + h*64 + n]));
    }
    // zero sWh + sFh (contiguous 2304 words) so first phase-4 adds zeros
    for (int g = tid; g < 2304; g += 256) sm[OW_WH + g] = 0.f;
    if (tid < 64) {
        sBe[tid]  = g_be[h*64 + tid];
        sBfx[tid] = b_fx[h*64 + tid];
    }
    float tmp = temperature[h];
    tmp = fminf(fmaxf(tmp, 0.5f), 5.0f);
    const float invT = 1.0f / tmp;

    const int warp = tid >> 5, lane = tid & 31;
    const int lg4 = lane >> 2, lm4 = lane & 3;

    const int mat = warp >> 2;             // 0: logits(We), 1: fx(Wfx)
    const int n0  = (warp & 3) * 16;

    const int mt = warp & 3;               // phase-4 s-tile
    const int nh = warp >> 2;              // phase-4 d-half

    // ---- ldmatrix per-lane addresses (bytes, shared space) ----
    const uint32_t sb = smem_u32(sm);
    const int Lm  = lane & 15;
    const int hiK = lane >> 4;
    const uint32_t aA = sb + (uint32_t)(OW_X + Lm*132 + hiK*4) * 4u;
    const uint32_t aB = sb + (uint32_t)((mat ? OW_WFX : OW_WE) + (n0 + Lm)*132 + hiK*4) * 4u;
    // phase-4 (trans, half buffers)
    const int tRow = ((lane >> 4) << 3) + (lane & 7);
    const int oct  = (lane >> 3) & 1;
    const uint32_t aW4 = sb + (uint32_t)(OW_WH)*4u + (uint32_t)(tRow*72 + mt*16 + oct*8) * 2u;
    const uint32_t aF4 = sb + (uint32_t)(OW_FH)*4u + (uint32_t)(tRow*72 + nh*32 + oct*8) * 2u;

    float accT[4][4];
    #pragma unroll
    for (int i = 0; i < 4; i++)
        #pragma unroll
        for (int j = 0; j < 4; j++) accT[i][j] = 0.f;
    float accN0 = 0.f, accN1 = 0.f;        // softmax-warp register norm partials

    const float* xbase = x + (size_t)b * N_ * C_;

    // ---- prologue: stage first x tile (all 256 threads) ----
    {
        const float* xp = xbase + (size_t)cidx * TS * C_;
        for (int g = tid; g < 2048; g += 256) {
            float4 v = ((const float4*)xp)[g];
            int row = g >> 6, kp0 = (g & 63) << 1;
            uint2 u;
            u.x = h2u(__floats2half2_rn(v.x, v.y));
            u.y = h2u(__floats2half2_rn(v.z, v.w));
            *(uint2*)&sX2[row*132 + kp0] = u;
        }
    }

    for (int chunk = cidx; chunk < NCHUNK; chunk += PC) {
        __syncthreads();   // A: sX2 / sWh / sFh all visible

        // ---- phase 2 + phase 4 MMAs in one continuous tensor burst ----
        float c2[2][2][4];
        #pragma unroll
        for (int m = 0; m < 2; m++)
            #pragma unroll
            for (int n = 0; n < 2; n++)
                #pragma unroll
                for (int j = 0; j < 4; j++) c2[m][n][j] = 0.f;

        #pragma unroll
        for (int ks = 0; ks < 16; ks++) {
            uint32_t A0[4], A1[4], Bv[4];
            ldsm4(A0, aA + ks*32u);
            ldsm4(A1, aA + ks*32u + 16u*132u*4u);
            ldsm4(Bv, aB + ks*32u);
            uint32_t b0[2] = { Bv[0], Bv[2] };
            uint32_t b1[2] = { Bv[1], Bv[3] };
            mma_f16(c2[0][0], A0, b0);
            mma_f16(c2[0][1], A0, b1);
            mma_f16(c2[1][0], A1, b0);
            mma_f16(c2[1][1], A1, b1);
        }
        // phase 4 for PREVIOUS chunk (zeros on first iteration)
        #pragma unroll
        for (int kstep = 0; kstep < 2; kstep++) {
            uint32_t kb = (uint32_t)(kstep * 16 * 72 * 2);
            uint32_t Aw[4], F0[4], F1[4];
            ldsm4t(Aw, aW4 + kb);
            ldsm4t(F0, aF4 + kb);
            ldsm4t(F1, aF4 + kb + 16u*2u);
            uint32_t fb0[2] = { F0[0], F0[2] };
            uint32_t fb1[2] = { F0[1], F0[3] };
            uint32_t fb2[2] = { F1[0], F1[2] };
            uint32_t fb3[2] = { F1[1], F1[3] };
            mma_f16(accT[0], Aw, fb0);
            mma_f16(accT[1], Aw, fb1);
            mma_f16(accT[2], Aw, fb2);
            mma_f16(accT[3], Aw, fb3);
        }
        __syncthreads();   // B: all MMA reads of sX2/sWh/sFh complete

        // ---- epilogue: logits -> sLG (warps 0-3); fx+bias -> sFh (warps 4-7) ----
        #pragma unroll
        for (int m = 0; m < 2; m++) {
            #pragma unroll
            for (int nt = 0; nt < 2; nt++) {
                int r = m*16 + lg4;
                int cc = n0 + nt*8 + (lm4 << 1);
                if (mat == 0) {
                    *(float2*)&sLG[r*72 + cc]     = make_float2(c2[m][nt][0], c2[m][nt][1]);
                    *(float2*)&sLG[(r+8)*72 + cc] = make_float2(c2[m][nt][2], c2[m][nt][3]);
                } else {
                    float2 bv = *(float2*)&sBfx[cc];
                    *(uint32_t*)&sFh[r*72 + cc] =
                        h2u(__floats2half2_rn(c2[m][nt][0] + bv.x, c2[m][nt][1] + bv.y));
                    *(uint32_t*)&sFh[(r+8)*72 + cc] =
                        h2u(__floats2half2_rn(c2[m][nt][2] + bv.x, c2[m][nt][3] + bv.y));
                }
            }
        }

        if (warp < 4) {
            // quarter-CTA barrier: only the logit producers/consumers sync
            asm volatile("bar.sync 1, 128;" ::: "memory");
            // ---- phase 3: softmax, 8 tokens per warp, norm in registers ----
            float2 be = *(float2*)&sBe[lane << 1];
            #pragma unroll
            for (int i = 0; i < 8; i++) {
                int t = warp*8 + i;
                float2 lg = *(float2*)&sLG[t*72 + (lane << 1)];
                float l0 = (lg.x + be.x) * invT;
                float l1 = (lg.y + be.y) * invT;
                float m = fmaxf(l0, l1);
                #pragma unroll
                for (int off = 16; off; off >>= 1)
                    m = fmaxf(m, __shfl_xor_sync(0xffffffffu, m, off));
                float e0 = __expf(l0 - m), e1 = __expf(l1 - m);
                float ss = e0 + e1;
                #pragma unroll
                for (int off = 16; off; off >>= 1)
                    ss += __shfl_xor_sync(0xffffffffu, ss, off);
                float inv = __frcp_rn(ss);
                float w0 = e0 * inv, w1 = e1 * inv;
                accN0 += w0; accN1 += w1;
                *(uint32_t*)&sWh[t*72 + (lane << 1)] = h2u(__floats2half2_rn(w0, w1));
            }
        } else {
            // ---- warps 4-7: stage next x tile concurrently with softmax ----
            int nchunk = chunk + PC;
            if (nchunk < NCHUNK) {
                const float* xp = xbase + (size_t)nchunk * TS * C_;
                int t128 = tid - 128;
                for (int g = t128; g < 2048; g += 128) {
                    float4 v = ((const float4*)xp)[g];
                    int row = g >> 6, kp0 = (g & 63) << 1;
                    uint2 u;
                    u.x = h2u(__floats2half2_rn(v.x, v.y));
                    u.y = h2u(__floats2half2_rn(v.z, v.w));
                    *(uint2*)&sX2[row*132 + kp0] = u;
                }
            }
        }
    }

    // ---- tail: phase 4 for the final chunk ----
    __syncthreads();
    #pragma unroll
    for (int kstep = 0; kstep < 2; kstep++) {
        uint32_t kb = (uint32_t)(kstep * 16 * 72 * 2);
        uint32_t Aw[4], F0[4], F1[4];
        ldsm4t(Aw, aW4 + kb);
        ldsm4t(F0, aF4 + kb);
        ldsm4t(F1, aF4 + kb + 16u*2u);
        uint32_t fb0[2] = { F0[0], F0[2] };
        uint32_t fb1[2] = { F0[1], F0[3] };
        uint32_t fb2[2] = { F1[0], F1[2] };
        uint32_t fb3[2] = { F1[1], F1[3] };
        mma_f16(accT[0], Aw, fb0);
        mma_f16(accT[1], Aw, fb1);
        mma_f16(accT[2], Aw, fb2);
        mma_f16(accT[3], Aw, fb3);
    }

    // ---- flush partials ----
    float* dst = g_T + pair * 4096;
    #pragma unroll
    for (int nt = 0; nt < 4; nt++) {
        int s0 = mt*16 + lg4;
        int d0 = nh*32 + nt*8 + (lm4 << 1);
        atomicAdd(&dst[s0*64 + d0],        accT[nt][0]);
        atomicAdd(&dst[s0*64 + d0 + 1],    accT[nt][1]);
        atomicAdd(&dst[(s0+8)*64 + d0],    accT[nt][2]);
        atomicAdd(&dst[(s0+8)*64 + d0+1],  accT[nt][3]);
    }
    if (warp < 4) {
        atomicAdd(&g_norm[pair*64 + (lane << 1)],     accN0);
        atomicAdd(&g_norm[pair*64 + (lane << 1) + 1], accN1);
    }
}

// K2: final normalization
__global__ void norm_kernel(float* __restrict__ out) {
    int idx = blockIdx.x * blockDim.x + threadIdx.x;
    int ps = idx >> 6;
    out[idx] = g_T[idx] / (g_norm[ps] + 0.01f);
}

extern "C" void kernel_launch(void* const* d_in, const int* in_sizes, int n_in,
                              void* d_out, int out_size) {
    const float* x    = (const float*)d_in[0];
    const float* W_x  = (const float*)d_in[1];
    const float* b_x  = (const float*)d_in[2];
    const float* W_fx = (const float*)d_in[3];
    const float* b_fx = (const float*)d_in[4];
    const float* W_s  = (const float*)d_in[5];
    const float* b_s  = (const float*)d_in[6];
    const float* temp = (const float*)d_in[7];
    float* out = (float*)d_out;

    cudaFuncSetAttribute(fused_kernel, cudaFuncAttributeMaxDynamicSharedMemorySize,
                         SMEM_WORDS * (int)sizeof(float));

    prep_kernel<<<512, 256>>>(W_x, b_x, W_s, b_s);
    fused_kernel<<<16 * PC, 256, SMEM_WORDS * sizeof(float)>>>(x, W_fx, b_fx, temp);
    norm_kernel<<<256, 256>>>(out);
}